// round 15
// baseline (speedup 1.0000x reference)
#include <cuda_runtime.h>
#include <cuda_fp16.h>
#include <cstdint>

// ---------------- problem constants ----------------
#define B_WIN 4096
#define NTOK  49
#define DIM   192
#define HEADS 6
#define HD    32
#define MTOT  (B_WIN * NTOK)            // 200704 rows
#define QKV_N (3 * DIM)                 // 576
#define SCALE 0.17677669529663687f      // 1/sqrt(32)

// ---------------- scratch (device globals: no allocs allowed) ----------------
__device__ __half g_xh    [(size_t)MTOT * DIM];                    // x in half
__device__ __half g_wqkvh [QKV_N * DIM];                           // qkv_w half
__device__ __half g_wprojh[DIM * DIM];                             // proj_w half
__device__ __half g_qkvh  [(size_t)3 * B_WIN * HEADS * NTOK * HD]; // [3,B,H,49,32]
__device__ __half g_biash [HEADS * 4224];                          // [H][64*66] masked bias, half

// ---------------- helpers ----------------
__device__ __forceinline__ unsigned packh2(float a, float b) {
    __half2 h = __floats2half2_rn(a, b);
    return *reinterpret_cast<unsigned*>(&h);
}

__device__ __forceinline__ void mma16(float* c, const unsigned* a, const unsigned* b) {
    asm volatile(
        "mma.sync.aligned.m16n8k16.row.col.f32.f16.f16.f32 "
        "{%0,%1,%2,%3},{%4,%5,%6,%7},{%8,%9},{%0,%1,%2,%3};\n"
        : "+f"(c[0]), "+f"(c[1]), "+f"(c[2]), "+f"(c[3])
        : "r"(a[0]), "r"(a[1]), "r"(a[2]), "r"(a[3]), "r"(b[0]), "r"(b[1]));
}

__device__ __forceinline__ uint32_t smem_u32(const void* p) {
    uint32_t a;
    asm("{ .reg .u64 t; cvta.to.shared.u64 t, %1; cvt.u32.u64 %0, t; }" : "=r"(a) : "l"(p));
    return a;
}

__device__ __forceinline__ void cpasync16(uint32_t dst, const void* src) {
    asm volatile("cp.async.ca.shared.global [%0], [%1], 16;" :: "r"(dst), "l"(src));
}
__device__ __forceinline__ void cpasync16z(uint32_t dst, const void* src, int srcsize) {
    asm volatile("cp.async.ca.shared.global [%0], [%1], 16, %2;"
                 :: "r"(dst), "l"(src), "r"(srcsize));
}
#define CP_COMMIT() asm volatile("cp.async.commit_group;" ::: "memory")
#define CP_WAIT(N)  asm volatile("cp.async.wait_group %0;" :: "n"(N) : "memory")
#define BAR_SYNC(id, cnt) asm volatile("bar.sync %0, %1;" :: "r"(id), "r"(cnt) : "memory")

// ---------------- prepass: x fp32 -> half ----------------
__global__ void cvt_x(const float* __restrict__ src, int n4) {
    int i = blockIdx.x * blockDim.x + threadIdx.x;
    if (i >= n4) return;
    float4 v = reinterpret_cast<const float4*>(src)[i];
    uint2 u; u.x = packh2(v.x, v.y); u.y = packh2(v.z, v.w);
    reinterpret_cast<uint2*>(g_xh)[i] = u;
}

// ---------------- prepass: weights + masked bias in one launch ----------------
__global__ void prep_small(const float* __restrict__ qkv_w, const float* __restrict__ proj_w,
                           const float* __restrict__ bias_table, const int* __restrict__ rel_index) {
    int i = blockIdx.x * blockDim.x + threadIdx.x;
    if (i < 27648) {
        float4 v = reinterpret_cast<const float4*>(qkv_w)[i];
        uint2 u; u.x = packh2(v.x, v.y); u.y = packh2(v.z, v.w);
        reinterpret_cast<uint2*>(g_wqkvh)[i] = u;
    } else if (i < 36864) {
        int j = i - 27648;
        float4 v = reinterpret_cast<const float4*>(proj_w)[j];
        uint2 u; u.x = packh2(v.x, v.y); u.y = packh2(v.z, v.w);
        reinterpret_cast<uint2*>(g_wprojh)[j] = u;
    } else if (i < 36864 + HEADS * 4224) {
        int j = i - 36864;
        int h = j / 4224;
        int r2 = j - h * 4224;
        int ii = r2 / 66, jj = r2 - ii * 66;
        float v = -60000.0f;
        if (ii < NTOK && jj < NTOK) v = bias_table[rel_index[ii * NTOK + jj] * HEADS + h];
        g_biash[j] = __float2half_rn(v);
    }
}

// ---------------- GEMM0: qkv = x @ qkv_w^T + bias ----------------
// Block tile 128x144, 6 warps (2m x 3n), warp tile 64x48, k-tile 64, 2-stage cp.async.
// Stage layout (words): A 128x36 (=4608) | B 144x36 (=5184); stage = 9792 words.
#define STG_WORDS 9792
#define G_SMEM_BYTES (2 * STG_WORDS * 4)

__device__ __forceinline__ void stage_tile(uint32_t sbase, int m0, int n0, int kb, int tid) {
    // A: 128 rows x 8 chunks = 1024; B: 144 rows x 8 chunks = 1152; total 2176
    for (int i = tid; i < 2176; i += 192) {
        if (i < 1024) {
            const int r = i >> 3, c = i & 7;
            cpasync16(sbase + (uint32_t)(r * 36 + c * 4) * 4,
                      g_xh + (size_t)(m0 + r) * 192 + kb + c * 8);
        } else {
            const int j = i - 1024;
            const int r = j >> 3, c = j & 7;
            cpasync16(sbase + (uint32_t)(4608 + r * 36 + c * 4) * 4,
                      g_wqkvh + (size_t)(n0 + r) * 192 + kb + c * 8);
        }
    }
}

__device__ __forceinline__ void compute_tile(const unsigned* buf, float acc[4][6][4],
                                             int wm, int wn, int g, int t) {
    const unsigned* As = buf;
    const unsigned* Bs = buf + 4608;
#pragma unroll
    for (int ks = 0; ks < 4; ks++) {
        const int kw = ks * 8;
        unsigned a[4][4], bf[6][2];
#pragma unroll
        for (int mf = 0; mf < 4; mf++) {
            const int base = (wm + mf * 16 + g) * 36 + kw + t;
            a[mf][0] = As[base];
            a[mf][1] = As[base + 8 * 36];
            a[mf][2] = As[base + 4];
            a[mf][3] = As[base + 8 * 36 + 4];
        }
#pragma unroll
        for (int nf = 0; nf < 6; nf++) {
            const int base = (wn + nf * 8 + g) * 36 + kw + t;
            bf[nf][0] = Bs[base];
            bf[nf][1] = Bs[base + 4];
        }
#pragma unroll
        for (int mf = 0; mf < 4; mf++)
#pragma unroll
            for (int nf = 0; nf < 6; nf++) mma16(acc[mf][nf], a[mf], bf[nf]);
    }
}

__global__ void __launch_bounds__(192) gemm0_kernel(const float* __restrict__ bias) {
    extern __shared__ __align__(16) unsigned sh[];
    const uint32_t sb = smem_u32(sh);

    const int tid = threadIdx.x;
    const int w = tid / 32, lane = tid & 31, g = lane >> 2, t = lane & 3;
    const int wm = (w / 3) * 64, wn = (w % 3) * 48;
    const int m0 = blockIdx.y * 128;
    const int n0 = blockIdx.x * 144;

    float acc[4][6][4];
#pragma unroll
    for (int mf = 0; mf < 4; mf++)
#pragma unroll
        for (int nf = 0; nf < 6; nf++)
#pragma unroll
            for (int v = 0; v < 4; v++) acc[mf][nf][v] = 0.f;

    stage_tile(sb,                 m0, n0, 0,  tid); CP_COMMIT();
    stage_tile(sb + STG_WORDS * 4, m0, n0, 64, tid); CP_COMMIT();

    CP_WAIT(1); __syncthreads();
    compute_tile(sh, acc, wm, wn, g, t);
    __syncthreads();
    stage_tile(sb, m0, n0, 128, tid); CP_COMMIT();

    CP_WAIT(1); __syncthreads();
    compute_tile(sh + STG_WORDS, acc, wm, wn, g, t);
    __syncthreads();

    CP_WAIT(0); __syncthreads();
    compute_tile(sh, acc, wm, wn, g, t);

    // ---- epilogue ----
#pragma unroll
    for (int mf = 0; mf < 4; mf++) {
        const int ma = m0 + wm + mf * 16 + g;
        const int mb = ma + 8;
        const int wa = ma / 49, ta = ma - wa * 49;
        const int wb = mb / 49, tb = mb - wb * 49;
#pragma unroll
        for (int nf = 0; nf < 6; nf++) {
            const int gc = n0 + wn + nf * 8 + 2 * t;
            float2 bb = __ldg(reinterpret_cast<const float2*>(bias + gc));
            float v00 = acc[mf][nf][0] + bb.x;
            float v01 = acc[mf][nf][1] + bb.y;
            float v10 = acc[mf][nf][2] + bb.x;
            float v11 = acc[mf][nf][3] + bb.y;
            if (gc < 192) { v00 *= SCALE; v01 *= SCALE; v10 *= SCALE; v11 *= SCALE; }
            const int s  = gc / 192;
            const int hh = (gc - s * 192) >> 5;
            const int d  = gc & 31;
            __half2* pa = reinterpret_cast<__half2*>(
                g_qkvh + ((((size_t)s * B_WIN + wa) * HEADS + hh) * NTOK + ta) * HD + d);
            __half2* pb = reinterpret_cast<__half2*>(
                g_qkvh + ((((size_t)s * B_WIN + wb) * HEADS + hh) * NTOK + tb) * HD + d);
            *pa = __floats2half2_rn(v00, v01);
            *pb = __floats2half2_rn(v10, v11);
        }
    }
}

// ---------------- fused attention + proj: one block per window, 256 threads ----------------
// Phase 1: 3 rounds x 2 heads, NAMED barrier per head-parity group; direct softmax;
// column tokens 56-63 (j=7) are all padding -> their S/bias/exp work is skipped
// entirely (sacc[7] stays 0, exactly matching exp(-60000)=0).
// Phase 2: proj from smem attn_out, W double-buffered in dead k/v region.
#define F_SMEM_BYTES (23040 * 4)
#define PLANE ((size_t)B_WIN * HEADS * NTOK * HD)

__global__ void __launch_bounds__(256, 2) fused_attn_proj(const float* __restrict__ proj_b,
                                                          float* __restrict__ out) {
    extern __shared__ __align__(16) unsigned sm[];
    const int tid = threadIdx.x;
    const int b = blockIdx.x;
    const uint32_t smb = smem_u32(sm);

    // ---- stage q,k,v for all 6 heads (zfill pad rows >= 49) ----
#pragma unroll
    for (int it = 0; it < 18; it++) {
        const int idx = tid + it * 256;
        const int s = idx / 1536;
        const int rem = idx - s * 1536;
        const int h = rem >> 8;
        const int rr = (rem >> 2) & 63;
        const int cc = idx & 3;
        const __half* src = g_qkvh + s * PLANE + ((size_t)b * HEADS + h) * (NTOK * HD)
                          + (rr < NTOK ? rr : 0) * HD + cc * 8;
        const uint32_t dst = smb + (uint32_t)(s * 7680 + h * 1280 + rr * 20 + cc * 4) * 4;
        cpasync16z(dst, src, rr < NTOK ? 16 : 0);
    }
    CP_COMMIT(); CP_WAIT(0);
    __syncthreads();

    const int w = tid >> 5, lane = tid & 31, g = lane >> 2, t = lane & 3;
    const int wq = w >> 2;            // head parity group (0/1)
    const int rg = w & 3;             // 16-row group
    const int i0 = rg * 16 + g, i1 = i0 + 8;

    const uint32_t row_off = (uint32_t)((((lane & 7) + ((lane >> 3) & 1) * 8) * 20) * 4);
    const uint32_t nb_hi = (uint32_t)(lane >> 4);

    // ---- phase 1: 3 rounds x 2 heads ----
    for (int r = 0; r < 3; r++) {
        const int head = 2 * r + wq;
        const unsigned* qs = sm + head * 1280;
        const unsigned* ks = sm + 7680 + head * 1280;
        const uint32_t vsb = smb + (uint32_t)(15360 + head * 1280) * 4;
        const __half2* bh2g = reinterpret_cast<const __half2*>(g_biash + head * 4224);

        float sacc[8][4];
#pragma unroll
        for (int j = 0; j < 8; j++)
#pragma unroll
            for (int v = 0; v < 4; v++) sacc[j][v] = 0.f;

#pragma unroll
        for (int ks2 = 0; ks2 < 2; ks2++) {
            const int kw = ks2 * 8;
            unsigned a[4] = { qs[i0 * 20 + kw + t], qs[i1 * 20 + kw + t],
                              qs[i0 * 20 + kw + t + 4], qs[i1 * 20 + kw + t + 4] };
#pragma unroll
            for (int j = 0; j < 7; j++) {           // j=7: all-padding columns, skip
                unsigned bf[2] = { ks[(j * 8 + g) * 20 + kw + t],
                                   ks[(j * 8 + g) * 20 + kw + t + 4] };
                mma16(sacc[j], a, bf);
            }
        }

        // ---- bias add + direct softmax (mask baked in; j=7 contributes exactly 0) ----
        float s0 = 0.f, s1 = 0.f;
#pragma unroll
        for (int j = 0; j < 7; j++) {
            float2 b0 = __half22float2(__ldg(bh2g + i0 * 33 + j * 4 + t));
            float2 b1 = __half22float2(__ldg(bh2g + i1 * 33 + j * 4 + t));
            float p0 = __expf(sacc[j][0] + b0.x); sacc[j][0] = p0; s0 += p0;
            float p1 = __expf(sacc[j][1] + b0.y); sacc[j][1] = p1; s0 += p1;
            float p2 = __expf(sacc[j][2] + b1.x); sacc[j][2] = p2; s1 += p2;
            float p3 = __expf(sacc[j][3] + b1.y); sacc[j][3] = p3; s1 += p3;
        }
        s0 += __shfl_xor_sync(0xffffffffu, s0, 1);
        s0 += __shfl_xor_sync(0xffffffffu, s0, 2);
        s1 += __shfl_xor_sync(0xffffffffu, s1, 1);
        s1 += __shfl_xor_sync(0xffffffffu, s1, 2);

        float oacc[4][4];
#pragma unroll
        for (int nb = 0; nb < 4; nb++)
#pragma unroll
            for (int v = 0; v < 4; v++) oacc[nb][v] = 0.f;

#pragma unroll
        for (int kk = 0; kk < 4; kk++) {
            unsigned a[4] = { packh2(sacc[2 * kk][0],     sacc[2 * kk][1]),
                              packh2(sacc[2 * kk][2],     sacc[2 * kk][3]),
                              packh2(sacc[2 * kk + 1][0], sacc[2 * kk + 1][1]),
                              packh2(sacc[2 * kk + 1][2], sacc[2 * kk + 1][3]) };
#pragma unroll
            for (int hn = 0; hn < 2; hn++) {
                const uint32_t nbb = 2 * hn + nb_hi;
                const uint32_t addr = vsb + (uint32_t)(kk * 1280) + row_off + nbb * 16;
                uint32_t r0, r1, r2, r3;
                asm volatile("ldmatrix.sync.aligned.m8n8.x4.trans.shared.b16 {%0,%1,%2,%3}, [%4];"
                             : "=r"(r0), "=r"(r1), "=r"(r2), "=r"(r3) : "r"(addr));
                unsigned b0[2] = { r0, r1 };
                unsigned b1[2] = { r2, r3 };
                mma16(oacc[2 * hn], a, b0);
                mma16(oacc[2 * hn + 1], a, b1);
            }
        }

        // only the 4 warps of this head group read this head's q/k/v -> group barrier
        BAR_SYNC(1 + wq, 128);

        const float inv0 = 1.f / s0, inv1 = 1.f / s1;
        unsigned* aout = sm + head * 1280;
#pragma unroll
        for (int nb = 0; nb < 4; nb++) {
            aout[i0 * 20 + nb * 4 + t] = packh2(oacc[nb][0] * inv0, oacc[nb][1] * inv0);
            aout[i1 * 20 + nb * 4 + t] = packh2(oacc[nb][2] * inv1, oacc[nb][3] * inv1);
        }
    }
    __syncthreads();   // attn_out visible to all; k/v region now dead

    // ---- phase 2: out = attn_out @ proj_w^T + proj_b ----
    const int wm = (w >> 2) * 32, wn = (w & 3) * 48;

    float acc[2][6][4];
#pragma unroll
    for (int mf = 0; mf < 2; mf++)
#pragma unroll
        for (int nf = 0; nf < 6; nf++)
#pragma unroll
            for (int v = 0; v < 4; v++) acc[mf][nf][v] = 0.f;

    const uint32_t bw0 = smb + 7680u * 4, bw1 = smb + 14592u * 4;
#pragma unroll
    for (int k = 0; k < 6; k++) {
        const int i = tid + k * 256;
        const int rW = i >> 3, c = i & 7;
        cpasync16(bw0 + (uint32_t)(rW * 36 + c * 4) * 4, g_wprojh + rW * 192 + 0 + c * 8);
    }
    CP_COMMIT();
#pragma unroll
    for (int k = 0; k < 6; k++) {
        const int i = tid + k * 256;
        const int rW = i >> 3, c = i & 7;
        cpasync16(bw1 + (uint32_t)(rW * 36 + c * 4) * 4, g_wprojh + rW * 192 + 64 + c * 8);
    }
    CP_COMMIT();

    for (int kt = 0; kt < 3; kt++) {
        if (kt == 0) { CP_WAIT(1); } else if (kt == 1) { CP_WAIT(1); } else { CP_WAIT(0); }
        __syncthreads();
        const unsigned* Bs = (kt == 1) ? (sm + 14592) : (sm + 7680);
#pragma unroll
        for (int s = 0; s < 4; s++) {
            const int ks2 = kt * 4 + s;
            const int abase = (ks2 >> 1) * 1280 + ((ks2 & 1) << 3) + t;
            unsigned a[2][4], bf[6][2];
#pragma unroll
            for (int mf = 0; mf < 2; mf++) {
                const int row = wm + mf * 16 + g;
                a[mf][0] = sm[abase + row * 20];
                a[mf][1] = sm[abase + (row + 8) * 20];
                a[mf][2] = sm[abase + row * 20 + 4];
                a[mf][3] = sm[abase + (row + 8) * 20 + 4];
            }
#pragma unroll
            for (int nf = 0; nf < 6; nf++) {
                const int bb = (wn + nf * 8 + g) * 36 + s * 8 + t;
                bf[nf][0] = Bs[bb];
                bf[nf][1] = Bs[bb + 4];
            }
#pragma unroll
            for (int mf = 0; mf < 2; mf++)
#pragma unroll
                for (int nf = 0; nf < 6; nf++) mma16(acc[mf][nf], a[mf], bf[nf]);
        }
        if (kt == 0) {
            __syncthreads();
#pragma unroll
            for (int k = 0; k < 6; k++) {
                const int i = tid + k * 256;
                const int rW = i >> 3, c = i & 7;
                cpasync16(bw0 + (uint32_t)(rW * 36 + c * 4) * 4,
                          g_wprojh + rW * 192 + 128 + c * 8);
            }
            CP_COMMIT();
        }
    }

#pragma unroll
    for (int mf = 0; mf < 2; mf++) {
        const int ma = wm + mf * 16 + g;
        const int mb = ma + 8;
#pragma unroll
        for (int nf = 0; nf < 6; nf++) {
            const int gc = wn + nf * 8 + 2 * t;
            float2 bb = __ldg(reinterpret_cast<const float2*>(proj_b + gc));
            if (ma < NTOK)
                *reinterpret_cast<float2*>(out + ((size_t)b * NTOK + ma) * DIM + gc) =
                    make_float2(acc[mf][nf][0] + bb.x, acc[mf][nf][1] + bb.y);
            if (mb < NTOK)
                *reinterpret_cast<float2*>(out + ((size_t)b * NTOK + mb) * DIM + gc) =
                    make_float2(acc[mf][nf][2] + bb.x, acc[mf][nf][3] + bb.y);
        }
    }
}

// ---------------- launch ----------------
extern "C" void kernel_launch(void* const* d_in, const int* in_sizes, int n_in,
                              void* d_out, int out_size) {
    const float* x          = (const float*)d_in[0];
    const float* qkv_w      = (const float*)d_in[1];
    const float* qkv_b      = (const float*)d_in[2];
    const float* proj_w     = (const float*)d_in[3];
    const float* proj_b     = (const float*)d_in[4];
    const float* bias_table = (const float*)d_in[5];
    const int*   rel_index  = (const int*)d_in[6];
    float* out = (float*)d_out;

    cudaFuncSetAttribute(gemm0_kernel, cudaFuncAttributeMaxDynamicSharedMemorySize, G_SMEM_BYTES);
    cudaFuncSetAttribute(fused_attn_proj, cudaFuncAttributeMaxDynamicSharedMemorySize, F_SMEM_BYTES);

    const int nx = MTOT * DIM / 4;
    cvt_x<<<(nx + 255) / 256, 256>>>(x, nx);
    prep_small<<<(36864 + HEADS * 4224 + 255) / 256, 256>>>(qkv_w, proj_w, bias_table, rel_index);

    gemm0_kernel<<<dim3(QKV_N / 144, MTOT / 128), 192, G_SMEM_BYTES>>>(qkv_b);
    fused_attn_proj<<<B_WIN, 256, F_SMEM_BYTES>>>(proj_b, out);
}

// round 16
// speedup vs baseline: 1.2556x; 1.2556x over previous
#include <cuda_runtime.h>
#include <cuda_fp16.h>
#include <cstdint>

// ---------------- problem constants ----------------
#define B_WIN 4096
#define NTOK  49
#define DIM   192
#define HEADS 6
#define HD    32
#define MTOT  (B_WIN * NTOK)            // 200704 rows
#define QKV_N (3 * DIM)                 // 576
#define SCALE 0.17677669529663687f      // 1/sqrt(32)

// ---------------- scratch (device globals: no allocs allowed) ----------------
__device__ __half g_xh    [(size_t)MTOT * DIM];                    // x in half
__device__ __half g_wqkvh [QKV_N * DIM];                           // qkv_w half
__device__ __half g_wprojh[DIM * DIM];                             // proj_w half
__device__ __half g_qkvh  [(size_t)3 * B_WIN * HEADS * NTOK * HD]; // [3,B,H,49,32]
__device__ __half g_biash [HEADS * 4224];                          // [H][64*66] masked bias, half

// ---------------- helpers ----------------
__device__ __forceinline__ unsigned packh2(float a, float b) {
    __half2 h = __floats2half2_rn(a, b);
    return *reinterpret_cast<unsigned*>(&h);
}

__device__ __forceinline__ void mma16(float* c, const unsigned* a, const unsigned* b) {
    asm volatile(
        "mma.sync.aligned.m16n8k16.row.col.f32.f16.f16.f32 "
        "{%0,%1,%2,%3},{%4,%5,%6,%7},{%8,%9},{%0,%1,%2,%3};\n"
        : "+f"(c[0]), "+f"(c[1]), "+f"(c[2]), "+f"(c[3])
        : "r"(a[0]), "r"(a[1]), "r"(a[2]), "r"(a[3]), "r"(b[0]), "r"(b[1]));
}

__device__ __forceinline__ uint32_t smem_u32(const void* p) {
    uint32_t a;
    asm("{ .reg .u64 t; cvta.to.shared.u64 t, %1; cvt.u32.u64 %0, t; }" : "=r"(a) : "l"(p));
    return a;
}

__device__ __forceinline__ void cpasync16(uint32_t dst, const void* src) {
    asm volatile("cp.async.ca.shared.global [%0], [%1], 16;" :: "r"(dst), "l"(src));
}
__device__ __forceinline__ void cpasync16z(uint32_t dst, const void* src, int srcsize) {
    asm volatile("cp.async.ca.shared.global [%0], [%1], 16, %2;"
                 :: "r"(dst), "l"(src), "r"(srcsize));
}
#define CP_COMMIT() asm volatile("cp.async.commit_group;" ::: "memory")
#define CP_WAIT(N)  asm volatile("cp.async.wait_group %0;" :: "n"(N) : "memory")
#define BAR_SYNC(id, cnt) asm volatile("bar.sync %0, %1;" :: "r"(id), "r"(cnt) : "memory")

// ---------------- prepass: x fp32 -> half ----------------
__global__ void cvt_x(const float* __restrict__ src, int n4) {
    int i = blockIdx.x * blockDim.x + threadIdx.x;
    if (i >= n4) return;
    float4 v = reinterpret_cast<const float4*>(src)[i];
    uint2 u; u.x = packh2(v.x, v.y); u.y = packh2(v.z, v.w);
    reinterpret_cast<uint2*>(g_xh)[i] = u;
}

// ---------------- prepass: weights + masked bias in one launch ----------------
__global__ void prep_small(const float* __restrict__ qkv_w, const float* __restrict__ proj_w,
                           const float* __restrict__ bias_table, const int* __restrict__ rel_index) {
    int i = blockIdx.x * blockDim.x + threadIdx.x;
    if (i < 27648) {
        float4 v = reinterpret_cast<const float4*>(qkv_w)[i];
        uint2 u; u.x = packh2(v.x, v.y); u.y = packh2(v.z, v.w);
        reinterpret_cast<uint2*>(g_wqkvh)[i] = u;
    } else if (i < 36864) {
        int j = i - 27648;
        float4 v = reinterpret_cast<const float4*>(proj_w)[j];
        uint2 u; u.x = packh2(v.x, v.y); u.y = packh2(v.z, v.w);
        reinterpret_cast<uint2*>(g_wprojh)[j] = u;
    } else if (i < 36864 + HEADS * 4224) {
        int j = i - 36864;
        int h = j / 4224;
        int r2 = j - h * 4224;
        int ii = r2 / 66, jj = r2 - ii * 66;
        float v = -60000.0f;
        if (ii < NTOK && jj < NTOK) v = bias_table[rel_index[ii * NTOK + jj] * HEADS + h];
        g_biash[j] = __float2half_rn(v);
    }
}

// ---------------- GEMM0 (R14-proven): qkv = x @ qkv_w^T + bias ----------------
// Block tile 128x96, 4 warps (2x2), warp tile 64x48, k-tile 64, 2-stage cp.async.
#define STG_WORDS 8064
#define G_SMEM_BYTES (2 * STG_WORDS * 4)

__device__ __forceinline__ void stage_tile(uint32_t sbase, int m0, int n0, int kb, int tid) {
#pragma unroll
    for (int k = 0; k < 8; k++) {
        const int i = tid + k * 128;
        const int r = i >> 3, c = i & 7;
        cpasync16(sbase + (uint32_t)(r * 36 + c * 4) * 4,
                  g_xh + (size_t)(m0 + r) * 192 + kb + c * 8);
    }
#pragma unroll
    for (int k = 0; k < 6; k++) {
        const int i = tid + k * 128;
        const int r = i >> 3, c = i & 7;
        cpasync16(sbase + (uint32_t)(4608 + r * 36 + c * 4) * 4,
                  g_wqkvh + (size_t)(n0 + r) * 192 + kb + c * 8);
    }
}

__device__ __forceinline__ void compute_tile(const unsigned* buf, float acc[4][6][4],
                                             int wm, int wn, int g, int t) {
    const unsigned* As = buf;
    const unsigned* Bs = buf + 4608;
#pragma unroll
    for (int ks = 0; ks < 4; ks++) {
        const int kw = ks * 8;
        unsigned a[4][4], bf[6][2];
#pragma unroll
        for (int mf = 0; mf < 4; mf++) {
            const int base = (wm + mf * 16 + g) * 36 + kw + t;
            a[mf][0] = As[base];
            a[mf][1] = As[base + 8 * 36];
            a[mf][2] = As[base + 4];
            a[mf][3] = As[base + 8 * 36 + 4];
        }
#pragma unroll
        for (int nf = 0; nf < 6; nf++) {
            const int base = (wn + nf * 8 + g) * 36 + kw + t;
            bf[nf][0] = Bs[base];
            bf[nf][1] = Bs[base + 4];
        }
#pragma unroll
        for (int mf = 0; mf < 4; mf++)
#pragma unroll
            for (int nf = 0; nf < 6; nf++) mma16(acc[mf][nf], a[mf], bf[nf]);
    }
}

__global__ void __launch_bounds__(128) gemm0_kernel(const float* __restrict__ bias) {
    extern __shared__ __align__(16) unsigned sh[];
    const uint32_t sb = smem_u32(sh);

    const int tid = threadIdx.x;
    const int w = tid >> 5, lane = tid & 31, g = lane >> 2, t = lane & 3;
    const int wm = (w >> 1) * 64, wn = (w & 1) * 48;
    const int m0 = blockIdx.y * 128;
    const int n0 = blockIdx.x * 96;

    float acc[4][6][4];
#pragma unroll
    for (int mf = 0; mf < 4; mf++)
#pragma unroll
        for (int nf = 0; nf < 6; nf++)
#pragma unroll
            for (int v = 0; v < 4; v++) acc[mf][nf][v] = 0.f;

    stage_tile(sb,                 m0, n0, 0,  tid); CP_COMMIT();
    stage_tile(sb + STG_WORDS * 4, m0, n0, 64, tid); CP_COMMIT();

    CP_WAIT(1); __syncthreads();
    compute_tile(sh, acc, wm, wn, g, t);
    __syncthreads();
    stage_tile(sb, m0, n0, 128, tid); CP_COMMIT();

    CP_WAIT(1); __syncthreads();
    compute_tile(sh + STG_WORDS, acc, wm, wn, g, t);
    __syncthreads();

    CP_WAIT(0); __syncthreads();
    compute_tile(sh, acc, wm, wn, g, t);

    // ---- epilogue ----
#pragma unroll
    for (int mf = 0; mf < 4; mf++) {
        const int ma = m0 + wm + mf * 16 + g;
        const int mb = ma + 8;
        const int wa = ma / 49, ta = ma - wa * 49;
        const int wb = mb / 49, tb = mb - wb * 49;
#pragma unroll
        for (int nf = 0; nf < 6; nf++) {
            const int gc = n0 + wn + nf * 8 + 2 * t;
            float2 bb = __ldg(reinterpret_cast<const float2*>(bias + gc));
            float v00 = acc[mf][nf][0] + bb.x;
            float v01 = acc[mf][nf][1] + bb.y;
            float v10 = acc[mf][nf][2] + bb.x;
            float v11 = acc[mf][nf][3] + bb.y;
            if (gc < 192) { v00 *= SCALE; v01 *= SCALE; v10 *= SCALE; v11 *= SCALE; }
            const int s  = gc / 192;
            const int hh = (gc - s * 192) >> 5;
            const int d  = gc & 31;
            __half2* pa = reinterpret_cast<__half2*>(
                g_qkvh + ((((size_t)s * B_WIN + wa) * HEADS + hh) * NTOK + ta) * HD + d);
            __half2* pb = reinterpret_cast<__half2*>(
                g_qkvh + ((((size_t)s * B_WIN + wb) * HEADS + hh) * NTOK + tb) * HD + d);
            *pa = __floats2half2_rn(v00, v01);
            *pb = __floats2half2_rn(v10, v11);
        }
    }
}

// ---------------- fused attention + proj (R15-proven): one block per window, 256 thr ----------------
// Phase 1: 3 rounds x 2 heads, NAMED barrier per head-parity group; direct softmax;
// j=7 (padding columns) skipped entirely. Phase 2: proj, W double-buffered in dead k/v.
#define F_SMEM_BYTES (23040 * 4)
#define PLANE ((size_t)B_WIN * HEADS * NTOK * HD)

__global__ void __launch_bounds__(256, 2) fused_attn_proj(const float* __restrict__ proj_b,
                                                          float* __restrict__ out) {
    extern __shared__ __align__(16) unsigned sm[];
    const int tid = threadIdx.x;
    const int b = blockIdx.x;
    const uint32_t smb = smem_u32(sm);

    // ---- stage q,k,v for all 6 heads (zfill pad rows >= 49) ----
#pragma unroll
    for (int it = 0; it < 18; it++) {
        const int idx = tid + it * 256;
        const int s = idx / 1536;
        const int rem = idx - s * 1536;
        const int h = rem >> 8;
        const int rr = (rem >> 2) & 63;
        const int cc = idx & 3;
        const __half* src = g_qkvh + s * PLANE + ((size_t)b * HEADS + h) * (NTOK * HD)
                          + (rr < NTOK ? rr : 0) * HD + cc * 8;
        const uint32_t dst = smb + (uint32_t)(s * 7680 + h * 1280 + rr * 20 + cc * 4) * 4;
        cpasync16z(dst, src, rr < NTOK ? 16 : 0);
    }
    CP_COMMIT(); CP_WAIT(0);
    __syncthreads();

    const int w = tid >> 5, lane = tid & 31, g = lane >> 2, t = lane & 3;
    const int wq = w >> 2;            // head parity group (0/1)
    const int rg = w & 3;             // 16-row group
    const int i0 = rg * 16 + g, i1 = i0 + 8;

    const uint32_t row_off = (uint32_t)((((lane & 7) + ((lane >> 3) & 1) * 8) * 20) * 4);
    const uint32_t nb_hi = (uint32_t)(lane >> 4);

    // ---- phase 1: 3 rounds x 2 heads ----
    for (int r = 0; r < 3; r++) {
        const int head = 2 * r + wq;
        const unsigned* qs = sm + head * 1280;
        const unsigned* ks = sm + 7680 + head * 1280;
        const uint32_t vsb = smb + (uint32_t)(15360 + head * 1280) * 4;
        const __half2* bh2g = reinterpret_cast<const __half2*>(g_biash + head * 4224);

        float sacc[8][4];
#pragma unroll
        for (int j = 0; j < 8; j++)
#pragma unroll
            for (int v = 0; v < 4; v++) sacc[j][v] = 0.f;

#pragma unroll
        for (int ks2 = 0; ks2 < 2; ks2++) {
            const int kw = ks2 * 8;
            unsigned a[4] = { qs[i0 * 20 + kw + t], qs[i1 * 20 + kw + t],
                              qs[i0 * 20 + kw + t + 4], qs[i1 * 20 + kw + t + 4] };
#pragma unroll
            for (int j = 0; j < 7; j++) {           // j=7: all-padding columns, skip
                unsigned bf[2] = { ks[(j * 8 + g) * 20 + kw + t],
                                   ks[(j * 8 + g) * 20 + kw + t + 4] };
                mma16(sacc[j], a, bf);
            }
        }

        // ---- bias add + direct softmax (mask baked in; j=7 contributes exactly 0) ----
        float s0 = 0.f, s1 = 0.f;
#pragma unroll
        for (int j = 0; j < 7; j++) {
            float2 b0 = __half22float2(__ldg(bh2g + i0 * 33 + j * 4 + t));
            float2 b1 = __half22float2(__ldg(bh2g + i1 * 33 + j * 4 + t));
            float p0 = __expf(sacc[j][0] + b0.x); sacc[j][0] = p0; s0 += p0;
            float p1 = __expf(sacc[j][1] + b0.y); sacc[j][1] = p1; s0 += p1;
            float p2 = __expf(sacc[j][2] + b1.x); sacc[j][2] = p2; s1 += p2;
            float p3 = __expf(sacc[j][3] + b1.y); sacc[j][3] = p3; s1 += p3;
        }
        s0 += __shfl_xor_sync(0xffffffffu, s0, 1);
        s0 += __shfl_xor_sync(0xffffffffu, s0, 2);
        s1 += __shfl_xor_sync(0xffffffffu, s1, 1);
        s1 += __shfl_xor_sync(0xffffffffu, s1, 2);

        float oacc[4][4];
#pragma unroll
        for (int nb = 0; nb < 4; nb++)
#pragma unroll
            for (int v = 0; v < 4; v++) oacc[nb][v] = 0.f;

#pragma unroll
        for (int kk = 0; kk < 4; kk++) {
            unsigned a[4] = { packh2(sacc[2 * kk][0],     sacc[2 * kk][1]),
                              packh2(sacc[2 * kk][2],     sacc[2 * kk][3]),
                              packh2(sacc[2 * kk + 1][0], sacc[2 * kk + 1][1]),
                              packh2(sacc[2 * kk + 1][2], sacc[2 * kk + 1][3]) };
#pragma unroll
            for (int hn = 0; hn < 2; hn++) {
                const uint32_t nbb = 2 * hn + nb_hi;
                const uint32_t addr = vsb + (uint32_t)(kk * 1280) + row_off + nbb * 16;
                uint32_t r0, r1, r2, r3;
                asm volatile("ldmatrix.sync.aligned.m8n8.x4.trans.shared.b16 {%0,%1,%2,%3}, [%4];"
                             : "=r"(r0), "=r"(r1), "=r"(r2), "=r"(r3) : "r"(addr));
                unsigned b0[2] = { r0, r1 };
                unsigned b1[2] = { r2, r3 };
                mma16(oacc[2 * hn], a, b0);
                mma16(oacc[2 * hn + 1], a, b1);
            }
        }

        // only the 4 warps of this head group read this head's q/k/v -> group barrier
        BAR_SYNC(1 + wq, 128);

        const float inv0 = 1.f / s0, inv1 = 1.f / s1;
        unsigned* aout = sm + head * 1280;
#pragma unroll
        for (int nb = 0; nb < 4; nb++) {
            aout[i0 * 20 + nb * 4 + t] = packh2(oacc[nb][0] * inv0, oacc[nb][1] * inv0);
            aout[i1 * 20 + nb * 4 + t] = packh2(oacc[nb][2] * inv1, oacc[nb][3] * inv1);
        }
    }
    __syncthreads();   // attn_out visible to all; k/v region now dead

    // ---- phase 2: out = attn_out @ proj_w^T + proj_b ----
    const int wm = (w >> 2) * 32, wn = (w & 3) * 48;

    float acc[2][6][4];
#pragma unroll
    for (int mf = 0; mf < 2; mf++)
#pragma unroll
        for (int nf = 0; nf < 6; nf++)
#pragma unroll
            for (int v = 0; v < 4; v++) acc[mf][nf][v] = 0.f;

    const uint32_t bw0 = smb + 7680u * 4, bw1 = smb + 14592u * 4;
#pragma unroll
    for (int k = 0; k < 6; k++) {
        const int i = tid + k * 256;
        const int rW = i >> 3, c = i & 7;
        cpasync16(bw0 + (uint32_t)(rW * 36 + c * 4) * 4, g_wprojh + rW * 192 + 0 + c * 8);
    }
    CP_COMMIT();
#pragma unroll
    for (int k = 0; k < 6; k++) {
        const int i = tid + k * 256;
        const int rW = i >> 3, c = i & 7;
        cpasync16(bw1 + (uint32_t)(rW * 36 + c * 4) * 4, g_wprojh + rW * 192 + 64 + c * 8);
    }
    CP_COMMIT();

    for (int kt = 0; kt < 3; kt++) {
        if (kt == 0) { CP_WAIT(1); } else if (kt == 1) { CP_WAIT(1); } else { CP_WAIT(0); }
        __syncthreads();
        const unsigned* Bs = (kt == 1) ? (sm + 14592) : (sm + 7680);
#pragma unroll
        for (int s = 0; s < 4; s++) {
            const int ks2 = kt * 4 + s;
            const int abase = (ks2 >> 1) * 1280 + ((ks2 & 1) << 3) + t;
            unsigned a[2][4], bf[6][2];
#pragma unroll
            for (int mf = 0; mf < 2; mf++) {
                const int row = wm + mf * 16 + g;
                a[mf][0] = sm[abase + row * 20];
                a[mf][1] = sm[abase + (row + 8) * 20];
                a[mf][2] = sm[abase + row * 20 + 4];
                a[mf][3] = sm[abase + (row + 8) * 20 + 4];
            }
#pragma unroll
            for (int nf = 0; nf < 6; nf++) {
                const int bb = (wn + nf * 8 + g) * 36 + s * 8 + t;
                bf[nf][0] = Bs[bb];
                bf[nf][1] = Bs[bb + 4];
            }
#pragma unroll
            for (int mf = 0; mf < 2; mf++)
#pragma unroll
                for (int nf = 0; nf < 6; nf++) mma16(acc[mf][nf], a[mf], bf[nf]);
        }
        if (kt == 0) {
            __syncthreads();
#pragma unroll
            for (int k = 0; k < 6; k++) {
                const int i = tid + k * 256;
                const int rW = i >> 3, c = i & 7;
                cpasync16(bw0 + (uint32_t)(rW * 36 + c * 4) * 4,
                          g_wprojh + rW * 192 + 128 + c * 8);
            }
            CP_COMMIT();
        }
    }

#pragma unroll
    for (int mf = 0; mf < 2; mf++) {
        const int ma = wm + mf * 16 + g;
        const int mb = ma + 8;
#pragma unroll
        for (int nf = 0; nf < 6; nf++) {
            const int gc = wn + nf * 8 + 2 * t;
            float2 bb = __ldg(reinterpret_cast<const float2*>(proj_b + gc));
            if (ma < NTOK)
                *reinterpret_cast<float2*>(out + ((size_t)b * NTOK + ma) * DIM + gc) =
                    make_float2(acc[mf][nf][0] + bb.x, acc[mf][nf][1] + bb.y);
            if (mb < NTOK)
                *reinterpret_cast<float2*>(out + ((size_t)b * NTOK + mb) * DIM + gc) =
                    make_float2(acc[mf][nf][2] + bb.x, acc[mf][nf][3] + bb.y);
        }
    }
}

// ---------------- launch ----------------
extern "C" void kernel_launch(void* const* d_in, const int* in_sizes, int n_in,
                              void* d_out, int out_size) {
    const float* x          = (const float*)d_in[0];
    const float* qkv_w      = (const float*)d_in[1];
    const float* qkv_b      = (const float*)d_in[2];
    const float* proj_w     = (const float*)d_in[3];
    const float* proj_b     = (const float*)d_in[4];
    const float* bias_table = (const float*)d_in[5];
    const int*   rel_index  = (const int*)d_in[6];
    float* out = (float*)d_out;

    cudaFuncSetAttribute(gemm0_kernel, cudaFuncAttributeMaxDynamicSharedMemorySize, G_SMEM_BYTES);
    cudaFuncSetAttribute(fused_attn_proj, cudaFuncAttributeMaxDynamicSharedMemorySize, F_SMEM_BYTES);

    const int nx = MTOT * DIM / 4;
    cvt_x<<<(nx + 255) / 256, 256>>>(x, nx);
    prep_small<<<(36864 + HEADS * 4224 + 255) / 256, 256>>>(qkv_w, proj_w, bias_table, rel_index);

    gemm0_kernel<<<dim3(QKV_N / 96, MTOT / 128), 128, G_SMEM_BYTES>>>(qkv_b);
    fused_attn_proj<<<B_WIN, 256, F_SMEM_BYTES>>>(proj_b, out);
}

// round 17
// speedup vs baseline: 1.3408x; 1.0678x over previous
#include <cuda_runtime.h>
#include <cuda_fp16.h>
#include <cstdint>

// ---------------- problem constants ----------------
#define B_WIN 4096
#define NTOK  49
#define DIM   192
#define HEADS 6
#define HD    32
#define MTOT  (B_WIN * NTOK)            // 200704 rows
#define QKV_N (3 * DIM)                 // 576
#define SCALE 0.17677669529663687f      // 1/sqrt(32)

// ---------------- scratch (device globals: no allocs allowed) ----------------
__device__ __half g_xh    [(size_t)MTOT * DIM];                    // x in half
__device__ __half g_wqkvh [QKV_N * DIM];                           // qkv_w half
__device__ __half g_wprojh[DIM * DIM];                             // proj_w half
__device__ __half g_qkvh  [(size_t)3 * B_WIN * HEADS * NTOK * HD]; // [3,B,H,49,32]
__device__ __half g_biash [HEADS * 4224];                          // [H][64*66] masked bias, half

// ---------------- helpers ----------------
__device__ __forceinline__ unsigned packh2(float a, float b) {
    __half2 h = __floats2half2_rn(a, b);
    return *reinterpret_cast<unsigned*>(&h);
}

__device__ __forceinline__ void mma16(float* c, const unsigned* a, const unsigned* b) {
    asm volatile(
        "mma.sync.aligned.m16n8k16.row.col.f32.f16.f16.f32 "
        "{%0,%1,%2,%3},{%4,%5,%6,%7},{%8,%9},{%0,%1,%2,%3};\n"
        : "+f"(c[0]), "+f"(c[1]), "+f"(c[2]), "+f"(c[3])
        : "r"(a[0]), "r"(a[1]), "r"(a[2]), "r"(a[3]), "r"(b[0]), "r"(b[1]));
}

__device__ __forceinline__ uint32_t smem_u32(const void* p) {
    uint32_t a;
    asm("{ .reg .u64 t; cvta.to.shared.u64 t, %1; cvt.u32.u64 %0, t; }" : "=r"(a) : "l"(p));
    return a;
}

__device__ __forceinline__ void cpasync16(uint32_t dst, const void* src) {
    asm volatile("cp.async.ca.shared.global [%0], [%1], 16;" :: "r"(dst), "l"(src));
}
__device__ __forceinline__ void cpasync16z(uint32_t dst, const void* src, int srcsize) {
    asm volatile("cp.async.ca.shared.global [%0], [%1], 16, %2;"
                 :: "r"(dst), "l"(src), "r"(srcsize));
}
#define CP_COMMIT() asm volatile("cp.async.commit_group;" ::: "memory")
#define CP_WAIT(N)  asm volatile("cp.async.wait_group %0;" :: "n"(N) : "memory")
#define BAR_SYNC(id, cnt) asm volatile("bar.sync %0, %1;" :: "r"(id), "r"(cnt) : "memory")

// ---------------- prepass: x fp32 -> half ----------------
__global__ void cvt_x(const float* __restrict__ src, int n4) {
    int i = blockIdx.x * blockDim.x + threadIdx.x;
    if (i >= n4) return;
    float4 v = reinterpret_cast<const float4*>(src)[i];
    uint2 u; u.x = packh2(v.x, v.y); u.y = packh2(v.z, v.w);
    reinterpret_cast<uint2*>(g_xh)[i] = u;
}

// ---------------- prepass: weights + masked bias in one launch ----------------
__global__ void prep_small(const float* __restrict__ qkv_w, const float* __restrict__ proj_w,
                           const float* __restrict__ bias_table, const int* __restrict__ rel_index) {
    int i = blockIdx.x * blockDim.x + threadIdx.x;
    if (i < 27648) {
        float4 v = reinterpret_cast<const float4*>(qkv_w)[i];
        uint2 u; u.x = packh2(v.x, v.y); u.y = packh2(v.z, v.w);
        reinterpret_cast<uint2*>(g_wqkvh)[i] = u;
    } else if (i < 36864) {
        int j = i - 27648;
        float4 v = reinterpret_cast<const float4*>(proj_w)[j];
        uint2 u; u.x = packh2(v.x, v.y); u.y = packh2(v.z, v.w);
        reinterpret_cast<uint2*>(g_wprojh)[j] = u;
    } else if (i < 36864 + HEADS * 4224) {
        int j = i - 36864;
        int h = j / 4224;
        int r2 = j - h * 4224;
        int ii = r2 / 66, jj = r2 - ii * 66;
        float v = -60000.0f;
        if (ii < NTOK && jj < NTOK) v = bias_table[rel_index[ii * NTOK + jj] * HEADS + h];
        g_biash[j] = __float2half_rn(v);
    }
}

// ---------------- GEMM0: qkv = x @ qkv_w^T + bias ----------------
// Block tile 128x96, 4 warps (2x2), warp tile 64x48, k-tile 64, 2-stage cp.async.
// Epilogue bounces the output tile through smem for fully-coalesced 16B stores.
#define STG_WORDS 8064
#define G_SMEM_BYTES (2 * STG_WORDS * 4)

__device__ __forceinline__ void stage_tile(uint32_t sbase, int m0, int n0, int kb, int tid) {
#pragma unroll
    for (int k = 0; k < 8; k++) {
        const int i = tid + k * 128;
        const int r = i >> 3, c = i & 7;
        cpasync16(sbase + (uint32_t)(r * 36 + c * 4) * 4,
                  g_xh + (size_t)(m0 + r) * 192 + kb + c * 8);
    }
#pragma unroll
    for (int k = 0; k < 6; k++) {
        const int i = tid + k * 128;
        const int r = i >> 3, c = i & 7;
        cpasync16(sbase + (uint32_t)(4608 + r * 36 + c * 4) * 4,
                  g_wqkvh + (size_t)(n0 + r) * 192 + kb + c * 8);
    }
}

__device__ __forceinline__ void compute_tile(const unsigned* buf, float acc[4][6][4],
                                             int wm, int wn, int g, int t) {
    const unsigned* As = buf;
    const unsigned* Bs = buf + 4608;
#pragma unroll
    for (int ks = 0; ks < 4; ks++) {
        const int kw = ks * 8;
        unsigned a[4][4], bf[6][2];
#pragma unroll
        for (int mf = 0; mf < 4; mf++) {
            const int base = (wm + mf * 16 + g) * 36 + kw + t;
            a[mf][0] = As[base];
            a[mf][1] = As[base + 8 * 36];
            a[mf][2] = As[base + 4];
            a[mf][3] = As[base + 8 * 36 + 4];
        }
#pragma unroll
        for (int nf = 0; nf < 6; nf++) {
            const int base = (wn + nf * 8 + g) * 36 + kw + t;
            bf[nf][0] = Bs[base];
            bf[nf][1] = Bs[base + 4];
        }
#pragma unroll
        for (int mf = 0; mf < 4; mf++)
#pragma unroll
            for (int nf = 0; nf < 6; nf++) mma16(acc[mf][nf], a[mf], bf[nf]);
    }
}

__global__ void __launch_bounds__(128) gemm0_kernel(const float* __restrict__ bias) {
    extern __shared__ __align__(16) unsigned sh[];
    const uint32_t sb = smem_u32(sh);

    const int tid = threadIdx.x;
    const int w = tid >> 5, lane = tid & 31, g = lane >> 2, t = lane & 3;
    const int wm = (w >> 1) * 64, wn = (w & 1) * 48;
    const int m0 = blockIdx.y * 128;
    const int n0 = blockIdx.x * 96;

    float acc[4][6][4];
#pragma unroll
    for (int mf = 0; mf < 4; mf++)
#pragma unroll
        for (int nf = 0; nf < 6; nf++)
#pragma unroll
            for (int v = 0; v < 4; v++) acc[mf][nf][v] = 0.f;

    stage_tile(sb,                 m0, n0, 0,  tid); CP_COMMIT();
    stage_tile(sb + STG_WORDS * 4, m0, n0, 64, tid); CP_COMMIT();

    CP_WAIT(1); __syncthreads();
    compute_tile(sh, acc, wm, wn, g, t);
    __syncthreads();
    stage_tile(sb, m0, n0, 128, tid); CP_COMMIT();

    CP_WAIT(1); __syncthreads();
    compute_tile(sh + STG_WORDS, acc, wm, wn, g, t);
    __syncthreads();

    CP_WAIT(0); __syncthreads();
    compute_tile(sh, acc, wm, wn, g, t);

    // ---- epilogue: bias + scale -> smem tile (stride 52) -> coalesced 16B stores ----
    __syncthreads();                       // all warps done reading stage buffer 0

    const int s = n0 / 192;                // q/k/v plane (tile never straddles)
    const int cbase = n0 - s * 192;        // 0 or 96 within the plane
    const float qs = (s == 0) ? SCALE : 1.0f;
    unsigned* Cs = sh;                     // 128 rows x 52 words (48 data + 4 pad)

#pragma unroll
    for (int mf = 0; mf < 4; mf++) {
        const int ra = wm + mf * 16 + g;
        const int rb = ra + 8;
#pragma unroll
        for (int nf = 0; nf < 6; nf++) {
            const int lc = wn + nf * 8 + 2 * t;       // local col (even)
            float2 bb = __ldg(reinterpret_cast<const float2*>(bias + n0 + lc));
            Cs[ra * 52 + (lc >> 1)] = packh2((acc[mf][nf][0] + bb.x) * qs,
                                             (acc[mf][nf][1] + bb.y) * qs);
            Cs[rb * 52 + (lc >> 1)] = packh2((acc[mf][nf][2] + bb.x) * qs,
                                             (acc[mf][nf][3] + bb.y) * qs);
        }
    }
    __syncthreads();

    // 128 rows x 12 chunks (16B each, 8 halves) = 1536 chunks over 128 threads
#pragma unroll
    for (int it = 0; it < 12; it++) {
        const int i = tid + it * 128;
        const int r = i / 12, c = i - r * 12;
        const int m = m0 + r;
        const int wa = m / 49, ta = m - wa * 49;
        const int col = cbase + c * 8;
        const int hh = col >> 5, d0 = col & 31;
        uint4 u = *reinterpret_cast<const uint4*>(&Cs[r * 52 + c * 4]);
        *reinterpret_cast<uint4*>(
            g_qkvh + (((size_t)s * B_WIN + wa) * HEADS + hh) * (NTOK * HD) + ta * HD + d0) = u;
    }
}

// ---------------- fused attention + proj (R15-proven): one block per window, 256 thr ----------------
// Phase 1: 3 rounds x 2 heads, NAMED barrier per head-parity group; direct softmax;
// j=7 (padding columns) skipped entirely. Phase 2: proj, W double-buffered in dead k/v.
#define F_SMEM_BYTES (23040 * 4)
#define PLANE ((size_t)B_WIN * HEADS * NTOK * HD)

__global__ void __launch_bounds__(256, 2) fused_attn_proj(const float* __restrict__ proj_b,
                                                          float* __restrict__ out) {
    extern __shared__ __align__(16) unsigned sm[];
    const int tid = threadIdx.x;
    const int b = blockIdx.x;
    const uint32_t smb = smem_u32(sm);

    // ---- stage q,k,v for all 6 heads (zfill pad rows >= 49) ----
#pragma unroll
    for (int it = 0; it < 18; it++) {
        const int idx = tid + it * 256;
        const int s = idx / 1536;
        const int rem = idx - s * 1536;
        const int h = rem >> 8;
        const int rr = (rem >> 2) & 63;
        const int cc = idx & 3;
        const __half* src = g_qkvh + s * PLANE + ((size_t)b * HEADS + h) * (NTOK * HD)
                          + (rr < NTOK ? rr : 0) * HD + cc * 8;
        const uint32_t dst = smb + (uint32_t)(s * 7680 + h * 1280 + rr * 20 + cc * 4) * 4;
        cpasync16z(dst, src, rr < NTOK ? 16 : 0);
    }
    CP_COMMIT(); CP_WAIT(0);
    __syncthreads();

    const int w = tid >> 5, lane = tid & 31, g = lane >> 2, t = lane & 3;
    const int wq = w >> 2;            // head parity group (0/1)
    const int rg = w & 3;             // 16-row group
    const int i0 = rg * 16 + g, i1 = i0 + 8;

    const uint32_t row_off = (uint32_t)((((lane & 7) + ((lane >> 3) & 1) * 8) * 20) * 4);
    const uint32_t nb_hi = (uint32_t)(lane >> 4);

    // ---- phase 1: 3 rounds x 2 heads ----
    for (int r = 0; r < 3; r++) {
        const int head = 2 * r + wq;
        const unsigned* qs = sm + head * 1280;
        const unsigned* ks = sm + 7680 + head * 1280;
        const uint32_t vsb = smb + (uint32_t)(15360 + head * 1280) * 4;
        const __half2* bh2g = reinterpret_cast<const __half2*>(g_biash + head * 4224);

        float sacc[8][4];
#pragma unroll
        for (int j = 0; j < 8; j++)
#pragma unroll
            for (int v = 0; v < 4; v++) sacc[j][v] = 0.f;

#pragma unroll
        for (int ks2 = 0; ks2 < 2; ks2++) {
            const int kw = ks2 * 8;
            unsigned a[4] = { qs[i0 * 20 + kw + t], qs[i1 * 20 + kw + t],
                              qs[i0 * 20 + kw + t + 4], qs[i1 * 20 + kw + t + 4] };
#pragma unroll
            for (int j = 0; j < 7; j++) {           // j=7: all-padding columns, skip
                unsigned bf[2] = { ks[(j * 8 + g) * 20 + kw + t],
                                   ks[(j * 8 + g) * 20 + kw + t + 4] };
                mma16(sacc[j], a, bf);
            }
        }

        // ---- bias add + direct softmax (mask baked in; j=7 contributes exactly 0) ----
        float s0 = 0.f, s1 = 0.f;
#pragma unroll
        for (int j = 0; j < 7; j++) {
            float2 b0 = __half22float2(__ldg(bh2g + i0 * 33 + j * 4 + t));
            float2 b1 = __half22float2(__ldg(bh2g + i1 * 33 + j * 4 + t));
            float p0 = __expf(sacc[j][0] + b0.x); sacc[j][0] = p0; s0 += p0;
            float p1 = __expf(sacc[j][1] + b0.y); sacc[j][1] = p1; s0 += p1;
            float p2 = __expf(sacc[j][2] + b1.x); sacc[j][2] = p2; s1 += p2;
            float p3 = __expf(sacc[j][3] + b1.y); sacc[j][3] = p3; s1 += p3;
        }
        s0 += __shfl_xor_sync(0xffffffffu, s0, 1);
        s0 += __shfl_xor_sync(0xffffffffu, s0, 2);
        s1 += __shfl_xor_sync(0xffffffffu, s1, 1);
        s1 += __shfl_xor_sync(0xffffffffu, s1, 2);

        float oacc[4][4];
#pragma unroll
        for (int nb = 0; nb < 4; nb++)
#pragma unroll
            for (int v = 0; v < 4; v++) oacc[nb][v] = 0.f;

#pragma unroll
        for (int kk = 0; kk < 4; kk++) {
            unsigned a[4] = { packh2(sacc[2 * kk][0],     sacc[2 * kk][1]),
                              packh2(sacc[2 * kk][2],     sacc[2 * kk][3]),
                              packh2(sacc[2 * kk + 1][0], sacc[2 * kk + 1][1]),
                              packh2(sacc[2 * kk + 1][2], sacc[2 * kk + 1][3]) };
#pragma unroll
            for (int hn = 0; hn < 2; hn++) {
                const uint32_t nbb = 2 * hn + nb_hi;
                const uint32_t addr = vsb + (uint32_t)(kk * 1280) + row_off + nbb * 16;
                uint32_t r0, r1, r2, r3;
                asm volatile("ldmatrix.sync.aligned.m8n8.x4.trans.shared.b16 {%0,%1,%2,%3}, [%4];"
                             : "=r"(r0), "=r"(r1), "=r"(r2), "=r"(r3) : "r"(addr));
                unsigned b0[2] = { r0, r1 };
                unsigned b1[2] = { r2, r3 };
                mma16(oacc[2 * hn], a, b0);
                mma16(oacc[2 * hn + 1], a, b1);
            }
        }

        // only the 4 warps of this head group read this head's q/k/v -> group barrier
        BAR_SYNC(1 + wq, 128);

        const float inv0 = 1.f / s0, inv1 = 1.f / s1;
        unsigned* aout = sm + head * 1280;
#pragma unroll
        for (int nb = 0; nb < 4; nb++) {
            aout[i0 * 20 + nb * 4 + t] = packh2(oacc[nb][0] * inv0, oacc[nb][1] * inv0);
            aout[i1 * 20 + nb * 4 + t] = packh2(oacc[nb][2] * inv1, oacc[nb][3] * inv1);
        }
    }
    __syncthreads();   // attn_out visible to all; k/v region now dead

    // ---- phase 2: out = attn_out @ proj_w^T + proj_b ----
    const int wm = (w >> 2) * 32, wn = (w & 3) * 48;

    float acc[2][6][4];
#pragma unroll
    for (int mf = 0; mf < 2; mf++)
#pragma unroll
        for (int nf = 0; nf < 6; nf++)
#pragma unroll
            for (int v = 0; v < 4; v++) acc[mf][nf][v] = 0.f;

    const uint32_t bw0 = smb + 7680u * 4, bw1 = smb + 14592u * 4;
#pragma unroll
    for (int k = 0; k < 6; k++) {
        const int i = tid + k * 256;
        const int rW = i >> 3, c = i & 7;
        cpasync16(bw0 + (uint32_t)(rW * 36 + c * 4) * 4, g_wprojh + rW * 192 + 0 + c * 8);
    }
    CP_COMMIT();
#pragma unroll
    for (int k = 0; k < 6; k++) {
        const int i = tid + k * 256;
        const int rW = i >> 3, c = i & 7;
        cpasync16(bw1 + (uint32_t)(rW * 36 + c * 4) * 4, g_wprojh + rW * 192 + 64 + c * 8);
    }
    CP_COMMIT();

    for (int kt = 0; kt < 3; kt++) {
        if (kt == 0) { CP_WAIT(1); } else if (kt == 1) { CP_WAIT(1); } else { CP_WAIT(0); }
        __syncthreads();
        const unsigned* Bs = (kt == 1) ? (sm + 14592) : (sm + 7680);
#pragma unroll
        for (int s = 0; s < 4; s++) {
            const int ks2 = kt * 4 + s;
            const int abase = (ks2 >> 1) * 1280 + ((ks2 & 1) << 3) + t;
            unsigned a[2][4], bf[6][2];
#pragma unroll
            for (int mf = 0; mf < 2; mf++) {
                const int row = wm + mf * 16 + g;
                a[mf][0] = sm[abase + row * 20];
                a[mf][1] = sm[abase + (row + 8) * 20];
                a[mf][2] = sm[abase + row * 20 + 4];
                a[mf][3] = sm[abase + (row + 8) * 20 + 4];
            }
#pragma unroll
            for (int nf = 0; nf < 6; nf++) {
                const int bb = (wn + nf * 8 + g) * 36 + s * 8 + t;
                bf[nf][0] = Bs[bb];
                bf[nf][1] = Bs[bb + 4];
            }
#pragma unroll
            for (int mf = 0; mf < 2; mf++)
#pragma unroll
                for (int nf = 0; nf < 6; nf++) mma16(acc[mf][nf], a[mf], bf[nf]);
        }
        if (kt == 0) {
            __syncthreads();
#pragma unroll
            for (int k = 0; k < 6; k++) {
                const int i = tid + k * 256;
                const int rW = i >> 3, c = i & 7;
                cpasync16(bw0 + (uint32_t)(rW * 36 + c * 4) * 4,
                          g_wprojh + rW * 192 + 128 + c * 8);
            }
            CP_COMMIT();
        }
    }

#pragma unroll
    for (int mf = 0; mf < 2; mf++) {
        const int ma = wm + mf * 16 + g;
        const int mb = ma + 8;
#pragma unroll
        for (int nf = 0; nf < 6; nf++) {
            const int gc = wn + nf * 8 + 2 * t;
            float2 bb = __ldg(reinterpret_cast<const float2*>(proj_b + gc));
            if (ma < NTOK)
                *reinterpret_cast<float2*>(out + ((size_t)b * NTOK + ma) * DIM + gc) =
                    make_float2(acc[mf][nf][0] + bb.x, acc[mf][nf][1] + bb.y);
            if (mb < NTOK)
                *reinterpret_cast<float2*>(out + ((size_t)b * NTOK + mb) * DIM + gc) =
                    make_float2(acc[mf][nf][2] + bb.x, acc[mf][nf][3] + bb.y);
        }
    }
}

// ---------------- launch ----------------
extern "C" void kernel_launch(void* const* d_in, const int* in_sizes, int n_in,
                              void* d_out, int out_size) {
    const float* x          = (const float*)d_in[0];
    const float* qkv_w      = (const float*)d_in[1];
    const float* qkv_b      = (const float*)d_in[2];
    const float* proj_w     = (const float*)d_in[3];
    const float* proj_b     = (const float*)d_in[4];
    const float* bias_table = (const float*)d_in[5];
    const int*   rel_index  = (const int*)d_in[6];
    float* out = (float*)d_out;

    cudaFuncSetAttribute(gemm0_kernel, cudaFuncAttributeMaxDynamicSharedMemorySize, G_SMEM_BYTES);
    cudaFuncSetAttribute(fused_attn_proj, cudaFuncAttributeMaxDynamicSharedMemorySize, F_SMEM_BYTES);

    const int nx = MTOT * DIM / 4;
    cvt_x<<<(nx + 255) / 256, 256>>>(x, nx);
    prep_small<<<(36864 + HEADS * 4224 + 255) / 256, 256>>>(qkv_w, proj_w, bias_table, rel_index);

    gemm0_kernel<<<dim3(QKV_N / 96, MTOT / 128), 128, G_SMEM_BYTES>>>(qkv_b);
    fused_attn_proj<<<B_WIN, 256, F_SMEM_BYTES>>>(proj_b, out);
}